// round 13
// baseline (speedup 1.0000x reference)
#include <cuda_runtime.h>
#include <cuda_bf16.h>
#include <cstdint>

#define NX    16384
#define CI    32
#define CO    32
#define H1D   64
#define H2D   128
#define NBI   256
#define NBO   256
#define KSPLIT 32

// ---------------- device scratch ----------------
__device__ __nv_bfloat16 g_Bphi_hi[H2D * NX];   // [k][n] phi hidden (relu'd), bf16 hi
__device__ __nv_bfloat16 g_Bphi_lo[H2D * NX];   // residual
__device__ __nv_bfloat16 g_Apsi_hi[NX * H2D];   // [m][k] psi hidden, bf16 hi
__device__ __nv_bfloat16 g_Apsi_lo[NX * H2D];
__device__ float g_Tpart[KSPLIT * NBI * H2D];   // [sp][bi][k]  4.2 MB
__device__ float g_xsumpart[KSPLIT * NBI];      // [sp][bi]
__device__ float g_w3pt[CI * H2D * CO];         // [i][k][o]  512 KB
__device__ float g_S[8 * CO * CI];              // [b][o*32+i]
__device__ float g_U[NBO * H2D];                // [b*32+o][k] (scaled 1/NX)
__device__ float g_c[NBO];                      // (scaled 1/NX)

// ---------------- helpers ----------------
__device__ __forceinline__ uint32_t smem_u32(const void* p) {
    uint32_t a;
    asm("{ .reg .u64 t; cvta.to.shared.u64 t, %1; cvt.u32.u64 %0, t; }" : "=r"(a) : "l"(p));
    return a;
}
__device__ __forceinline__ void ldm4(uint32_t* r, uint32_t addr) {
    asm volatile("ldmatrix.sync.aligned.m8n8.x4.shared.b16 {%0,%1,%2,%3}, [%4];"
                 : "=r"(r[0]), "=r"(r[1]), "=r"(r[2]), "=r"(r[3]) : "r"(addr));
}
__device__ __forceinline__ void mma_bf16(float* c, const uint32_t* a, uint32_t b0, uint32_t b1) {
    asm volatile("mma.sync.aligned.m16n8k16.row.col.f32.bf16.bf16.f32 "
                 "{%0,%1,%2,%3}, {%4,%5,%6,%7}, {%8,%9}, {%0,%1,%2,%3};"
                 : "+f"(c[0]), "+f"(c[1]), "+f"(c[2]), "+f"(c[3])
                 : "r"(a[0]), "r"(a[1]), "r"(a[2]), "r"(a[3]), "r"(b0), "r"(b1));
}
__device__ __forceinline__ uint32_t pack2(__nv_bfloat16 a, __nv_bfloat16 b) {
    return (uint32_t)__bfloat16_as_ushort(a) | ((uint32_t)__bfloat16_as_ushort(b) << 16);
}
__device__ __forceinline__ void split1(float v, __nv_bfloat16& h, __nv_bfloat16& l) {
    h = __float2bfloat16(v);
    l = __float2bfloat16(v - __bfloat162float(h));
}

// SMEM tile geometry for GEMM1/2 (bf16): row stride 136 elems (272 B)
#define TSTR 136
#define ROWB 272
// k_g1: A = x (64 rows), B = phi (128 rows)
#define G1_AHI 0
#define G1_ALO 17408
#define G1_BHI 34816
#define G1_BLO 69632
#define G1_SMEM 104448
// k_g2: A = psi (128 rows), B = U (64 rows)
#define G2_AHI 0
#define G2_ALO 34816
#define G2_BHI 69632
#define G2_BLO 87040
#define G2_SMEM 104448
// k_mlp: A = h1 (128 n x 64 j), B = w2T (128 k x 64 j), stride 72 elems (144 B)
#define MSTR 72
#define M_AHI 0
#define M_ALO 18432
#define M_BHI 36864
#define M_BLO 55296
#define MLP_SMEM 73728

// ---------------- K1: coordinate MLPs, layer2 on tensor pipe ----------------
__global__ __launch_bounds__(256) void k_mlp(
    const float* __restrict__ w1p, const float* __restrict__ b1p,
    const float* __restrict__ w2p, const float* __restrict__ b2p,
    const float* __restrict__ w1q, const float* __restrict__ b1q,
    const float* __restrict__ w2q, const float* __restrict__ b2q)
{
    extern __shared__ char dsm[];
    __shared__ float sW1[2 * H1D];
    __shared__ float sB1[H1D];
    __shared__ float sB2[H2D];
    uint32_t sb = smem_u32(dsm);

    const bool psi = (blockIdx.y != 0);
    const float* w1 = psi ? w1q : w1p;
    const float* b1 = psi ? b1q : b1p;
    const float* w2 = psi ? w2q : w2p;
    const float* b2 = psi ? b2q : b2p;

    int t = threadIdx.x, wid = t >> 5, lane = t & 31;
    int n0 = blockIdx.x * 128;

    if (t < 2 * H1D) sW1[t] = w1[t];
    if (t < H1D)     sB1[t] = b1[t];
    if (t < H2D)     sB2[t] = b2[t];

    for (int idx = t; idx < H1D * H2D; idx += 256) {
        int k = idx & 127, j = idx >> 7;
        float v = w2[j * 128 + k];
        __nv_bfloat16 h, l; split1(v, h, l);
        uint32_t off = (uint32_t)((k * MSTR + j) * 2);
        *(__nv_bfloat16*)(dsm + M_BHI + off) = h;
        *(__nv_bfloat16*)(dsm + M_BLO + off) = l;
    }
    __syncthreads();

    {
        int nl = t >> 1;
        int n = n0 + nl;
        int j0 = (t & 1) * 32;
        const float inv = 1.0f / 127.0f;
        float gx = (float)(n >> 7) * inv;
        float gy = (float)(n & 127) * inv;
#pragma unroll
        for (int jj = 0; jj < 32; jj += 2) {
            int j = j0 + jj;
            float v0 = fmaxf(fmaf(gx, sW1[j],     fmaf(gy, sW1[H1D + j],     sB1[j])),     0.0f);
            float v1 = fmaxf(fmaf(gx, sW1[j + 1], fmaf(gy, sW1[H1D + j + 1], sB1[j + 1])), 0.0f);
            __nv_bfloat16 h0, l0, h1v, l1; split1(v0, h0, l0); split1(v1, h1v, l1);
            uint32_t off = (uint32_t)((nl * MSTR + j) * 2);
            *(uint32_t*)(dsm + M_AHI + off) = pack2(h0, h1v);
            *(uint32_t*)(dsm + M_ALO + off) = pack2(l0, l1);
        }
    }
    __syncthreads();

    int m_w = (wid & 3) * 32;
    int j_w = (wid >> 2) * 64;
    int lrow = lane & 15, lcol = (lane >> 4) * 8;
    int grp = lane >> 2, tig = lane & 3;

    float C[2][8][4];
#pragma unroll
    for (int a = 0; a < 2; a++)
#pragma unroll
        for (int b = 0; b < 8; b++)
#pragma unroll
            for (int d = 0; d < 4; d++) C[a][b][d] = 0.0f;

#pragma unroll
    for (int ks = 0; ks < 4; ks++) {
        int c0 = ks * 16;
        uint32_t ah[8], al[8], bh[16], bl[16];
#pragma unroll
        for (int mi = 0; mi < 2; mi++) {
            uint32_t ro = (uint32_t)(((m_w + mi * 16 + lrow) * MSTR + c0 + lcol) * 2);
            ldm4(ah + mi * 4, sb + M_AHI + ro);
            ldm4(al + mi * 4, sb + M_ALO + ro);
        }
#pragma unroll
        for (int q = 0; q < 4; q++) {
            uint32_t ro = (uint32_t)(((j_w + q * 16 + lrow) * MSTR + c0 + lcol) * 2);
            ldm4(bh + q * 4, sb + M_BHI + ro);
            ldm4(bl + q * 4, sb + M_BLO + ro);
        }
#pragma unroll
        for (int mi = 0; mi < 2; mi++)
#pragma unroll
            for (int q = 0; q < 4; q++) {
                mma_bf16(C[mi][2*q],   ah + mi*4, bh[q*4+0], bh[q*4+2]);
                mma_bf16(C[mi][2*q],   ah + mi*4, bl[q*4+0], bl[q*4+2]);
                mma_bf16(C[mi][2*q],   al + mi*4, bh[q*4+0], bh[q*4+2]);
                mma_bf16(C[mi][2*q+1], ah + mi*4, bh[q*4+1], bh[q*4+3]);
                mma_bf16(C[mi][2*q+1], ah + mi*4, bl[q*4+1], bl[q*4+3]);
                mma_bf16(C[mi][2*q+1], al + mi*4, bh[q*4+1], bh[q*4+3]);
            }
    }
    __syncthreads();

    float* sO = (float*)dsm;
#pragma unroll
    for (int mi = 0; mi < 2; mi++)
#pragma unroll
        for (int jj = 0; jj < 8; jj++) {
            int j = j_w + jj * 8 + tig * 2;
            int i = m_w + mi * 16 + grp;
            sO[i * 133 + j]           = C[mi][jj][0];
            sO[i * 133 + j + 1]       = C[mi][jj][1];
            sO[(i + 8) * 133 + j]     = C[mi][jj][2];
            sO[(i + 8) * 133 + j + 1] = C[mi][jj][3];
        }
    __syncthreads();

    if (!psi) {
        for (int idx = t; idx < 16384; idx += 256) {
            int k = idx >> 7, r = idx & 127;
            float v = fmaxf(sO[r * 133 + k] + sB2[k], 0.0f);
            __nv_bfloat16 h, l; split1(v, h, l);
            size_t a = (size_t)k * NX + n0 + r;
            g_Bphi_hi[a] = h;
            g_Bphi_lo[a] = l;
        }
    } else {
        for (int idx = t; idx < 16384; idx += 256) {
            int row = idx >> 7, k = idx & 127;
            float v = fmaxf(sO[row * 133 + k] + sB2[k], 0.0f);
            __nv_bfloat16 h, l; split1(v, h, l);
            size_t a = (size_t)(n0 + row) * H2D + k;
            g_Apsi_hi[a] = h;
            g_Apsi_lo[a] = l;
        }
    }
}

// ---------------- k_tr: w3p[k][o*32+i] -> w3pt[i][k][o] (both sides coalesced) ------
__global__ __launch_bounds__(256) void k_tr(const float* __restrict__ w3p)
{
    __shared__ float sm[32 * 33];          // [o][i] pad 33
    int k = blockIdx.x, t = threadIdx.x;
    for (int it = 0; it < 4; it++) {
        int col = it * 256 + t;            // coalesced read
        sm[(col >> 5) * 33 + (col & 31)] = w3p[k * 1024 + col];
    }
    __syncthreads();
    for (int it = 0; it < 4; it++) {
        int idx = it * 256 + t;
        int i = idx >> 5, o = idx & 31;    // consecutive t -> consecutive o: coalesced write
        g_w3pt[i * 4096 + k * 32 + o] = sm[o * 33 + i];
    }
}

// ---------------- GEMM1 (mma.sync) + fused xsum partials -----------------------------
__global__ __launch_bounds__(256, 2) void k_g1(const float* __restrict__ x)
{
    extern __shared__ char dsm[];
    uint32_t sb = smem_u32(dsm);
    int t = threadIdx.x, wid = t >> 5, lane = t & 31;
    int bi0 = blockIdx.x * 64;
    int n0 = blockIdx.y * 512;
    int m_w = (wid & 1) * 32;
    int j_w = (wid >> 1) * 32;
    int lrow = lane & 15, lcol = (lane >> 4) * 8;
    int grp = lane >> 2, tig = lane & 3;

    float C[2][4][4];
#pragma unroll
    for (int a = 0; a < 2; a++)
#pragma unroll
        for (int b = 0; b < 4; b++)
#pragma unroll
            for (int d = 0; d < 4; d++) C[a][b][d] = 0.0f;

    float xs[8];
#pragma unroll
    for (int i = 0; i < 8; i++) xs[i] = 0.0f;

    for (int ch = 0; ch < 4; ch++) {
        int nb = n0 + ch * 128;
#pragma unroll
        for (int it = 0; it < 8; it++) {
            int idx = t + it * 256;
            int row = idx >> 5, nq = idx & 31;
            float4 v = *(const float4*)(x + (size_t)(bi0 + row) * NX + nb + nq * 4);
            xs[it] += (v.x + v.y) + (v.z + v.w);
            __nv_bfloat16 h0,h1,h2,h3,l0,l1,l2,l3;
            split1(v.x,h0,l0); split1(v.y,h1,l1); split1(v.z,h2,l2); split1(v.w,h3,l3);
            uint32_t off = (uint32_t)(row * ROWB + nq * 8);
            *(uint2*)(dsm + G1_AHI + off) = make_uint2(pack2(h0,h1), pack2(h2,h3));
            *(uint2*)(dsm + G1_ALO + off) = make_uint2(pack2(l0,l1), pack2(l2,l3));
        }
        for (int idx = t; idx < 2048; idx += 256) {
            int row = idx >> 4, n8 = idx & 15;
            size_t ga = (size_t)row * NX + nb + n8 * 8;
            uint32_t off = (uint32_t)(row * ROWB + n8 * 16);
            *(uint4*)(dsm + G1_BHI + off) = *(const uint4*)(g_Bphi_hi + ga);
            *(uint4*)(dsm + G1_BLO + off) = *(const uint4*)(g_Bphi_lo + ga);
        }
        __syncthreads();

#pragma unroll
        for (int ks = 0; ks < 8; ks++) {
            int c0 = ks * 16;
            uint32_t ah[8], al[8], bh[8], bl[8];
#pragma unroll
            for (int mi = 0; mi < 2; mi++) {
                uint32_t ro = (uint32_t)(((m_w + mi * 16 + lrow) * TSTR + c0 + lcol) * 2);
                ldm4(ah + mi * 4, sb + G1_AHI + ro);
                ldm4(al + mi * 4, sb + G1_ALO + ro);
            }
#pragma unroll
            for (int q = 0; q < 2; q++) {
                uint32_t ro = (uint32_t)(((j_w + q * 16 + lrow) * TSTR + c0 + lcol) * 2);
                ldm4(bh + q * 4, sb + G1_BHI + ro);
                ldm4(bl + q * 4, sb + G1_BLO + ro);
            }
#pragma unroll
            for (int mi = 0; mi < 2; mi++)
#pragma unroll
                for (int q = 0; q < 2; q++) {
                    mma_bf16(C[mi][2*q],   ah + mi*4, bh[q*4+0], bh[q*4+2]);
                    mma_bf16(C[mi][2*q],   ah + mi*4, bl[q*4+0], bl[q*4+2]);
                    mma_bf16(C[mi][2*q],   al + mi*4, bh[q*4+0], bh[q*4+2]);
                    mma_bf16(C[mi][2*q+1], ah + mi*4, bh[q*4+1], bh[q*4+3]);
                    mma_bf16(C[mi][2*q+1], ah + mi*4, bl[q*4+1], bl[q*4+3]);
                    mma_bf16(C[mi][2*q+1], al + mi*4, bh[q*4+1], bh[q*4+3]);
                }
        }
        __syncthreads();
    }

#pragma unroll
    for (int mi = 0; mi < 2; mi++)
#pragma unroll
        for (int jj = 0; jj < 4; jj++) {
            int j = j_w + jj * 8 + tig * 2;
            int bi_l = m_w + mi * 16 + grp;
            size_t a0 = ((size_t)blockIdx.y * 256 + bi0 + bi_l) * 128 + j;
            *(float2*)(g_Tpart + a0)          = make_float2(C[mi][jj][0], C[mi][jj][1]);
            *(float2*)(g_Tpart + a0 + 8*128)  = make_float2(C[mi][jj][2], C[mi][jj][3]);
        }

#pragma unroll
    for (int i = 0; i < 8; i++) {
        float v = xs[i];
#pragma unroll
        for (int o = 16; o; o >>= 1) v += __shfl_xor_sync(0xffffffffu, v, o);
        if (lane == 0)
            g_xsumpart[blockIdx.y * 256 + bi0 + wid + 8 * i] = v;
    }
}

// ---------------- k_s3: fused split-K reduce + s (grid 256 = bi rows, 512 thr) -------
__global__ __launch_bounds__(512) void k_s3(const float* __restrict__ b3p)
{
    __shared__ float sPart[4][128];
    __shared__ float sT[128];
    __shared__ float sXs;
    __shared__ float smc[16][32];
    int bi = blockIdx.x, t = threadIdx.x;
    int b = bi >> 5, i = bi & 31;

    // 4-way sp sweep: thread (p, k) sums 8 partials (coalesced per warp)
    {
        int k = t & 127, p = t >> 7;
        float acc = 0.0f;
        const float* tp = g_Tpart + (size_t)(p * 8) * (NBI * H2D) + (size_t)bi * 128 + k;
#pragma unroll
        for (int sp = 0; sp < 8; sp++)
            acc += tp[(size_t)sp * (NBI * H2D)];
        sPart[p][k] = acc;
    }
    // xsum (fixed-order warp reduce, deterministic)
    if (t < 32) {
        float v = g_xsumpart[t * 256 + bi];
#pragma unroll
        for (int off = 16; off; off >>= 1) v += __shfl_xor_sync(0xffffffffu, v, off);
        if (t == 0) sXs = v;
    }
    __syncthreads();
    if (t < 128)
        sT[t] = (sPart[0][t] + sPart[1][t]) + (sPart[2][t] + sPart[3][t]);
    __syncthreads();

    // s: 16 partials per output o, 8-long each (wp coalesced over o; sT broadcast)
    {
        int o = t & 31, kq = t >> 5;           // kq = 0..15
        const float* wp = g_w3pt + (size_t)i * 4096 + (size_t)(kq * 8) * 32 + o;
        float acc = 0.0f;
#pragma unroll
        for (int j = 0; j < 8; j++)
            acc = fmaf(sT[kq * 8 + j], wp[j * 32], acc);
        smc[kq][o] = acc;
    }
    __syncthreads();
    if (t < 32) {
        float s = 0.0f;
#pragma unroll
        for (int kq = 0; kq < 16; kq++) s += smc[kq][t];   // fixed order
        int col = t * 32 + i;                  // o = t
        g_S[b * 1024 + col] = s + b3p[col] * sXs;
    }
}

// ---------------- k_u2: U[bo][k], c[bo] (grid 256 = (b,o), 256 thr) ----------------
__global__ __launch_bounds__(256) void k_u2(const float* __restrict__ w3q,
                                            const float* __restrict__ b3q)
{
    __shared__ float sW[128 * 33];
    __shared__ float sS[32];
    __shared__ float sPc[2][128];
    int bo = blockIdx.x, t = threadIdx.x;      // bo = b*32 + o
    int b = bo >> 5, o = bo & 31;
    for (int idx = t; idx < 4096; idx += 256) {
        int i = idx & 31, k = idx >> 5;
        sW[k * 33 + i] = w3q[k * 1024 + o * 32 + i];
    }
    if (t < 32) sS[t] = g_S[b * 1024 + o * 32 + t];
    __syncthreads();

    const float inv = 1.0f / (float)NX;
    {
        int k = t & 127, p = t >> 7;           // 2 halves of the ii-dot
        float u = 0.0f;
#pragma unroll
        for (int ii = 0; ii < 16; ii++)
            u = fmaf(sS[p * 16 + ii], sW[k * 33 + p * 16 + ii], u);
        sPc[p][k] = u;
    }
    __syncthreads();
    if (t < 128)
        g_U[(size_t)bo * 128 + t] = (sPc[0][t] + sPc[1][t]) * inv;
    if (t >= 128 && t < 160) {
        int tt = t - 128;
        float v = sS[tt] * b3q[o * 32 + tt];
#pragma unroll
        for (int off = 16; off; off >>= 1) v += __shfl_xor_sync(0xffffffffu, v, off);
        if (tt == 0) g_c[bo] = v * inv;
    }
}

// ---------------- GEMM2 (mma.sync): out[bo][m] = psi[m,k] * U[bo,k] + c ----------------
__global__ __launch_bounds__(256, 2) void k_g2(float* __restrict__ out)
{
    extern __shared__ char dsm[];
    __shared__ float sc[64];
    uint32_t sb = smem_u32(dsm);
    int t = threadIdx.x, wid = t >> 5, lane = t & 31;
    int m0 = blockIdx.x * 128;
    int bo0 = blockIdx.y * 64;
    int m_w = (wid & 3) * 32;
    int j_w = (wid >> 2) * 32;
    int lrow = lane & 15, lcol = (lane >> 4) * 8;
    int grp = lane >> 2, tig = lane & 3;

    if (t < 64) sc[t] = g_c[bo0 + t];

    for (int idx = t; idx < 2048; idx += 256) {
        int row = idx >> 4, k8 = idx & 15;
        size_t ga = (size_t)(m0 + row) * H2D + k8 * 8;
        uint32_t off = (uint32_t)(row * ROWB + k8 * 16);
        *(uint4*)(dsm + G2_AHI + off) = *(const uint4*)(g_Apsi_hi + ga);
        *(uint4*)(dsm + G2_ALO + off) = *(const uint4*)(g_Apsi_lo + ga);
    }
    for (int idx = t; idx < 2048; idx += 256) {
        int row = idx >> 5, kq = idx & 31;
        float4 v = *(const float4*)(g_U + (size_t)(bo0 + row) * 128 + kq * 4);
        __nv_bfloat16 h0,h1,h2,h3,l0,l1,l2,l3;
        split1(v.x,h0,l0); split1(v.y,h1,l1); split1(v.z,h2,l2); split1(v.w,h3,l3);
        uint32_t off = (uint32_t)(row * ROWB + kq * 8);
        *(uint2*)(dsm + G2_BHI + off) = make_uint2(pack2(h0,h1), pack2(h2,h3));
        *(uint2*)(dsm + G2_BLO + off) = make_uint2(pack2(l0,l1), pack2(l2,l3));
    }
    __syncthreads();

    float C[2][4][4];
#pragma unroll
    for (int a = 0; a < 2; a++)
#pragma unroll
        for (int b = 0; b < 4; b++)
#pragma unroll
            for (int d = 0; d < 4; d++) C[a][b][d] = 0.0f;

#pragma unroll
    for (int ks = 0; ks < 8; ks++) {
        int c0 = ks * 16;
        uint32_t ah[8], al[8], bh[8], bl[8];
#pragma unroll
        for (int mi = 0; mi < 2; mi++) {
            uint32_t ro = (uint32_t)(((m_w + mi * 16 + lrow) * TSTR + c0 + lcol) * 2);
            ldm4(ah + mi * 4, sb + G2_AHI + ro);
            ldm4(al + mi * 4, sb + G2_ALO + ro);
        }
#pragma unroll
        for (int q = 0; q < 2; q++) {
            uint32_t ro = (uint32_t)(((j_w + q * 16 + lrow) * TSTR + c0 + lcol) * 2);
            ldm4(bh + q * 4, sb + G2_BHI + ro);
            ldm4(bl + q * 4, sb + G2_BLO + ro);
        }
#pragma unroll
        for (int mi = 0; mi < 2; mi++)
#pragma unroll
            for (int q = 0; q < 2; q++) {
                mma_bf16(C[mi][2*q],   ah + mi*4, bh[q*4+0], bh[q*4+2]);
                mma_bf16(C[mi][2*q],   ah + mi*4, bl[q*4+0], bl[q*4+2]);
                mma_bf16(C[mi][2*q],   al + mi*4, bh[q*4+0], bh[q*4+2]);
                mma_bf16(C[mi][2*q+1], ah + mi*4, bh[q*4+1], bh[q*4+3]);
                mma_bf16(C[mi][2*q+1], ah + mi*4, bl[q*4+1], bl[q*4+3]);
                mma_bf16(C[mi][2*q+1], al + mi*4, bh[q*4+1], bh[q*4+3]);
            }
    }
    __syncthreads();

    float* sO = (float*)dsm;
#pragma unroll
    for (int mi = 0; mi < 2; mi++)
#pragma unroll
        for (int jj = 0; jj < 4; jj++) {
            int j = j_w + jj * 8 + tig * 2;
            int i = m_w + mi * 16 + grp;
            sO[j * 132 + i]           = C[mi][jj][0];
            sO[(j + 1) * 132 + i]     = C[mi][jj][1];
            sO[j * 132 + i + 8]       = C[mi][jj][2];
            sO[(j + 1) * 132 + i + 8] = C[mi][jj][3];
        }
    __syncthreads();
    for (int idx = t; idx < 8192; idx += 256) {
        int i = idx & 127, j = idx >> 7;
        out[(size_t)(bo0 + j) * NX + m0 + i] = sO[j * 132 + i] + sc[j];
    }
}

// ---------------- launch ----------------
extern "C" void kernel_launch(void* const* d_in, const int* in_sizes, int n_in,
                              void* d_out, int out_size)
{
    const float* x      = (const float*)d_in[0];
    const float* phi_w1 = (const float*)d_in[1];
    const float* phi_b1 = (const float*)d_in[2];
    const float* phi_w2 = (const float*)d_in[3];
    const float* phi_b2 = (const float*)d_in[4];
    const float* phi_w3 = (const float*)d_in[5];
    const float* phi_b3 = (const float*)d_in[6];
    const float* psi_w1 = (const float*)d_in[7];
    const float* psi_b1 = (const float*)d_in[8];
    const float* psi_w2 = (const float*)d_in[9];
    const float* psi_b2 = (const float*)d_in[10];
    const float* psi_w3 = (const float*)d_in[11];
    const float* psi_b3 = (const float*)d_in[12];
    float* out = (float*)d_out;

    cudaFuncSetAttribute(k_mlp, cudaFuncAttributeMaxDynamicSharedMemorySize, MLP_SMEM);
    cudaFuncSetAttribute(k_g1,  cudaFuncAttributeMaxDynamicSharedMemorySize, G1_SMEM);
    cudaFuncSetAttribute(k_g2,  cudaFuncAttributeMaxDynamicSharedMemorySize, G2_SMEM);

    k_tr<<<H2D, 256>>>(phi_w3);
    k_mlp<<<dim3(NX / 128, 2), 256, MLP_SMEM>>>(phi_w1, phi_b1, phi_w2, phi_b2,
                                                psi_w1, psi_b1, psi_w2, psi_b2);
    k_g1<<<dim3(4, KSPLIT), 256, G1_SMEM>>>(x);
    k_s3<<<NBI, 512>>>(phi_b3);
    k_u2<<<NBO, 256>>>(psi_w3, psi_b3);
    k_g2<<<dim3(NX / 128, 4), 256, G2_SMEM>>>(out);
}

// round 16
// speedup vs baseline: 1.0114x; 1.0114x over previous
#include <cuda_runtime.h>
#include <cuda_bf16.h>
#include <cstdint>

#define NX    16384
#define CI    32
#define CO    32
#define H1D   64
#define H2D   128
#define NBI   256
#define NBO   256
#define KSPLIT 32

// ---------------- device scratch ----------------
__device__ __nv_bfloat16 g_Bphi_hi[H2D * NX];   // [k][n] phi hidden (relu'd), bf16 hi
__device__ __nv_bfloat16 g_Bphi_lo[H2D * NX];   // residual
__device__ __nv_bfloat16 g_Apsi_hi[NX * H2D];   // [m][k] psi hidden, bf16 hi
__device__ __nv_bfloat16 g_Apsi_lo[NX * H2D];
__device__ float g_Tpart[KSPLIT * NBI * H2D];   // [sp][bi][k]  4.2 MB
__device__ float g_xsumpart[KSPLIT * NBI];      // [sp][bi]
__device__ float g_w3pt[CI * H2D * CO];         // [i][k][o]  512 KB
__device__ float g_S[8 * CO * CI];              // [b][o*32+i]
__device__ float g_U[NBO * H2D];                // [b*32+o][k] (scaled 1/NX)
__device__ float g_c[NBO];                      // (scaled 1/NX)

// ---------------- helpers ----------------
__device__ __forceinline__ uint32_t smem_u32(const void* p) {
    uint32_t a;
    asm("{ .reg .u64 t; cvta.to.shared.u64 t, %1; cvt.u32.u64 %0, t; }" : "=r"(a) : "l"(p));
    return a;
}
__device__ __forceinline__ void ldm4(uint32_t* r, uint32_t addr) {
    asm volatile("ldmatrix.sync.aligned.m8n8.x4.shared.b16 {%0,%1,%2,%3}, [%4];"
                 : "=r"(r[0]), "=r"(r[1]), "=r"(r[2]), "=r"(r[3]) : "r"(addr));
}
__device__ __forceinline__ void mma_bf16(float* c, const uint32_t* a, uint32_t b0, uint32_t b1) {
    asm volatile("mma.sync.aligned.m16n8k16.row.col.f32.bf16.bf16.f32 "
                 "{%0,%1,%2,%3}, {%4,%5,%6,%7}, {%8,%9}, {%0,%1,%2,%3};"
                 : "+f"(c[0]), "+f"(c[1]), "+f"(c[2]), "+f"(c[3])
                 : "r"(a[0]), "r"(a[1]), "r"(a[2]), "r"(a[3]), "r"(b0), "r"(b1));
}
__device__ __forceinline__ uint32_t pack2(__nv_bfloat16 a, __nv_bfloat16 b) {
    return (uint32_t)__bfloat16_as_ushort(a) | ((uint32_t)__bfloat16_as_ushort(b) << 16);
}
__device__ __forceinline__ void split1(float v, __nv_bfloat16& h, __nv_bfloat16& l) {
    h = __float2bfloat16(v);
    l = __float2bfloat16(v - __bfloat162float(h));
}

// SMEM tile geometry for GEMM1/2 (bf16): row stride 136 elems (272 B)
#define TSTR 136
#define ROWB 272
// k_g1: A = x (64 rows), B = phi (128 rows)
#define G1_AHI 0
#define G1_ALO 17408
#define G1_BHI 34816
#define G1_BLO 69632
#define G1_SMEM 104448
// k_g2: A = psi (128 rows), B = U (64 rows)
#define G2_AHI 0
#define G2_ALO 34816
#define G2_BHI 69632
#define G2_BLO 87040
#define G2_SMEM 104448
// k_mlp: A = h1 (128 n x 64 j), B = w2T (128 k x 64 j), stride 72 elems (144 B)
#define MSTR 72
#define M_AHI 0
#define M_ALO 18432
#define M_BHI 36864
#define M_BLO 55296
#define MLP_SMEM 73728

// ---------------- K1: coordinate MLPs, layer2 on tensor pipe ----------------
__global__ __launch_bounds__(256) void k_mlp(
    const float* __restrict__ w1p, const float* __restrict__ b1p,
    const float* __restrict__ w2p, const float* __restrict__ b2p,
    const float* __restrict__ w1q, const float* __restrict__ b1q,
    const float* __restrict__ w2q, const float* __restrict__ b2q)
{
    extern __shared__ char dsm[];
    __shared__ float sW1[2 * H1D];
    __shared__ float sB1[H1D];
    __shared__ float sB2[H2D];
    uint32_t sb = smem_u32(dsm);

    const bool psi = (blockIdx.y != 0);
    const float* w1 = psi ? w1q : w1p;
    const float* b1 = psi ? b1q : b1p;
    const float* w2 = psi ? w2q : w2p;
    const float* b2 = psi ? b2q : b2p;

    int t = threadIdx.x, wid = t >> 5, lane = t & 31;
    int n0 = blockIdx.x * 128;

    if (t < 2 * H1D) sW1[t] = w1[t];
    if (t < H1D)     sB1[t] = b1[t];
    if (t < H2D)     sB2[t] = b2[t];

    for (int idx = t; idx < H1D * H2D; idx += 256) {
        int k = idx & 127, j = idx >> 7;
        float v = w2[j * 128 + k];
        __nv_bfloat16 h, l; split1(v, h, l);
        uint32_t off = (uint32_t)((k * MSTR + j) * 2);
        *(__nv_bfloat16*)(dsm + M_BHI + off) = h;
        *(__nv_bfloat16*)(dsm + M_BLO + off) = l;
    }
    __syncthreads();

    {
        int nl = t >> 1;
        int n = n0 + nl;
        int j0 = (t & 1) * 32;
        const float inv = 1.0f / 127.0f;
        float gx = (float)(n >> 7) * inv;
        float gy = (float)(n & 127) * inv;
#pragma unroll
        for (int jj = 0; jj < 32; jj += 2) {
            int j = j0 + jj;
            float v0 = fmaxf(fmaf(gx, sW1[j],     fmaf(gy, sW1[H1D + j],     sB1[j])),     0.0f);
            float v1 = fmaxf(fmaf(gx, sW1[j + 1], fmaf(gy, sW1[H1D + j + 1], sB1[j + 1])), 0.0f);
            __nv_bfloat16 h0, l0, h1v, l1; split1(v0, h0, l0); split1(v1, h1v, l1);
            uint32_t off = (uint32_t)((nl * MSTR + j) * 2);
            *(uint32_t*)(dsm + M_AHI + off) = pack2(h0, h1v);
            *(uint32_t*)(dsm + M_ALO + off) = pack2(l0, l1);
        }
    }
    __syncthreads();

    int m_w = (wid & 3) * 32;
    int j_w = (wid >> 2) * 64;
    int lrow = lane & 15, lcol = (lane >> 4) * 8;
    int grp = lane >> 2, tig = lane & 3;

    float C[2][8][4];
#pragma unroll
    for (int a = 0; a < 2; a++)
#pragma unroll
        for (int b = 0; b < 8; b++)
#pragma unroll
            for (int d = 0; d < 4; d++) C[a][b][d] = 0.0f;

#pragma unroll
    for (int ks = 0; ks < 4; ks++) {
        int c0 = ks * 16;
        uint32_t ah[8], al[8], bh[16], bl[16];
#pragma unroll
        for (int mi = 0; mi < 2; mi++) {
            uint32_t ro = (uint32_t)(((m_w + mi * 16 + lrow) * MSTR + c0 + lcol) * 2);
            ldm4(ah + mi * 4, sb + M_AHI + ro);
            ldm4(al + mi * 4, sb + M_ALO + ro);
        }
#pragma unroll
        for (int q = 0; q < 4; q++) {
            uint32_t ro = (uint32_t)(((j_w + q * 16 + lrow) * MSTR + c0 + lcol) * 2);
            ldm4(bh + q * 4, sb + M_BHI + ro);
            ldm4(bl + q * 4, sb + M_BLO + ro);
        }
#pragma unroll
        for (int mi = 0; mi < 2; mi++)
#pragma unroll
            for (int q = 0; q < 4; q++) {
                mma_bf16(C[mi][2*q],   ah + mi*4, bh[q*4+0], bh[q*4+2]);
                mma_bf16(C[mi][2*q],   ah + mi*4, bl[q*4+0], bl[q*4+2]);
                mma_bf16(C[mi][2*q],   al + mi*4, bh[q*4+0], bh[q*4+2]);
                mma_bf16(C[mi][2*q+1], ah + mi*4, bh[q*4+1], bh[q*4+3]);
                mma_bf16(C[mi][2*q+1], ah + mi*4, bl[q*4+1], bl[q*4+3]);
                mma_bf16(C[mi][2*q+1], al + mi*4, bh[q*4+1], bh[q*4+3]);
            }
    }
    __syncthreads();

    float* sO = (float*)dsm;
#pragma unroll
    for (int mi = 0; mi < 2; mi++)
#pragma unroll
        for (int jj = 0; jj < 8; jj++) {
            int j = j_w + jj * 8 + tig * 2;
            int i = m_w + mi * 16 + grp;
            sO[i * 133 + j]           = C[mi][jj][0];
            sO[i * 133 + j + 1]       = C[mi][jj][1];
            sO[(i + 8) * 133 + j]     = C[mi][jj][2];
            sO[(i + 8) * 133 + j + 1] = C[mi][jj][3];
        }
    __syncthreads();

    if (!psi) {
        for (int idx = t; idx < 16384; idx += 256) {
            int k = idx >> 7, r = idx & 127;
            float v = fmaxf(sO[r * 133 + k] + sB2[k], 0.0f);
            __nv_bfloat16 h, l; split1(v, h, l);
            size_t a = (size_t)k * NX + n0 + r;
            g_Bphi_hi[a] = h;
            g_Bphi_lo[a] = l;
        }
    } else {
        for (int idx = t; idx < 16384; idx += 256) {
            int row = idx >> 7, k = idx & 127;
            float v = fmaxf(sO[row * 133 + k] + sB2[k], 0.0f);
            __nv_bfloat16 h, l; split1(v, h, l);
            size_t a = (size_t)(n0 + row) * H2D + k;
            g_Apsi_hi[a] = h;
            g_Apsi_lo[a] = l;
        }
    }
}

// ---------------- k_tr: w3p[k][o*32+i] -> w3pt[i][k][o] (both sides coalesced) ------
__global__ __launch_bounds__(256) void k_tr(const float* __restrict__ w3p)
{
    __shared__ float sm[32 * 33];          // [o][i] pad 33
    int k = blockIdx.x, t = threadIdx.x;
    for (int it = 0; it < 4; it++) {
        int col = it * 256 + t;            // coalesced read
        sm[(col >> 5) * 33 + (col & 31)] = w3p[k * 1024 + col];
    }
    __syncthreads();
    for (int it = 0; it < 4; it++) {
        int idx = it * 256 + t;
        int i = idx >> 5, o = idx & 31;    // consecutive t -> consecutive o: coalesced write
        g_w3pt[i * 4096 + k * 32 + o] = sm[o * 33 + i];
    }
}

// ---------------- GEMM1 (mma.sync) + fused xsum partials -----------------------------
__global__ __launch_bounds__(256, 2) void k_g1(const float* __restrict__ x)
{
    extern __shared__ char dsm[];
    uint32_t sb = smem_u32(dsm);
    int t = threadIdx.x, wid = t >> 5, lane = t & 31;
    int bi0 = blockIdx.x * 64;
    int n0 = blockIdx.y * 512;
    int m_w = (wid & 1) * 32;
    int j_w = (wid >> 1) * 32;
    int lrow = lane & 15, lcol = (lane >> 4) * 8;
    int grp = lane >> 2, tig = lane & 3;

    float C[2][4][4];
#pragma unroll
    for (int a = 0; a < 2; a++)
#pragma unroll
        for (int b = 0; b < 4; b++)
#pragma unroll
            for (int d = 0; d < 4; d++) C[a][b][d] = 0.0f;

    float xs[8];
#pragma unroll
    for (int i = 0; i < 8; i++) xs[i] = 0.0f;

    for (int ch = 0; ch < 4; ch++) {
        int nb = n0 + ch * 128;
#pragma unroll
        for (int it = 0; it < 8; it++) {
            int idx = t + it * 256;
            int row = idx >> 5, nq = idx & 31;
            float4 v = *(const float4*)(x + (size_t)(bi0 + row) * NX + nb + nq * 4);
            xs[it] += (v.x + v.y) + (v.z + v.w);
            __nv_bfloat16 h0,h1,h2,h3,l0,l1,l2,l3;
            split1(v.x,h0,l0); split1(v.y,h1,l1); split1(v.z,h2,l2); split1(v.w,h3,l3);
            uint32_t off = (uint32_t)(row * ROWB + nq * 8);
            *(uint2*)(dsm + G1_AHI + off) = make_uint2(pack2(h0,h1), pack2(h2,h3));
            *(uint2*)(dsm + G1_ALO + off) = make_uint2(pack2(l0,l1), pack2(l2,l3));
        }
        for (int idx = t; idx < 2048; idx += 256) {
            int row = idx >> 4, n8 = idx & 15;
            size_t ga = (size_t)row * NX + nb + n8 * 8;
            uint32_t off = (uint32_t)(row * ROWB + n8 * 16);
            *(uint4*)(dsm + G1_BHI + off) = *(const uint4*)(g_Bphi_hi + ga);
            *(uint4*)(dsm + G1_BLO + off) = *(const uint4*)(g_Bphi_lo + ga);
        }
        __syncthreads();

#pragma unroll
        for (int ks = 0; ks < 8; ks++) {
            int c0 = ks * 16;
            uint32_t ah[8], al[8], bh[8], bl[8];
#pragma unroll
            for (int mi = 0; mi < 2; mi++) {
                uint32_t ro = (uint32_t)(((m_w + mi * 16 + lrow) * TSTR + c0 + lcol) * 2);
                ldm4(ah + mi * 4, sb + G1_AHI + ro);
                ldm4(al + mi * 4, sb + G1_ALO + ro);
            }
#pragma unroll
            for (int q = 0; q < 2; q++) {
                uint32_t ro = (uint32_t)(((j_w + q * 16 + lrow) * TSTR + c0 + lcol) * 2);
                ldm4(bh + q * 4, sb + G1_BHI + ro);
                ldm4(bl + q * 4, sb + G1_BLO + ro);
            }
#pragma unroll
            for (int mi = 0; mi < 2; mi++)
#pragma unroll
                for (int q = 0; q < 2; q++) {
                    mma_bf16(C[mi][2*q],   ah + mi*4, bh[q*4+0], bh[q*4+2]);
                    mma_bf16(C[mi][2*q],   ah + mi*4, bl[q*4+0], bl[q*4+2]);
                    mma_bf16(C[mi][2*q],   al + mi*4, bh[q*4+0], bh[q*4+2]);
                    mma_bf16(C[mi][2*q+1], ah + mi*4, bh[q*4+1], bh[q*4+3]);
                    mma_bf16(C[mi][2*q+1], ah + mi*4, bl[q*4+1], bl[q*4+3]);
                    mma_bf16(C[mi][2*q+1], al + mi*4, bh[q*4+1], bh[q*4+3]);
                }
        }
        __syncthreads();
    }

#pragma unroll
    for (int mi = 0; mi < 2; mi++)
#pragma unroll
        for (int jj = 0; jj < 4; jj++) {
            int j = j_w + jj * 8 + tig * 2;
            int bi_l = m_w + mi * 16 + grp;
            size_t a0 = ((size_t)blockIdx.y * 256 + bi0 + bi_l) * 128 + j;
            *(float2*)(g_Tpart + a0)          = make_float2(C[mi][jj][0], C[mi][jj][1]);
            *(float2*)(g_Tpart + a0 + 8*128)  = make_float2(C[mi][jj][2], C[mi][jj][3]);
        }

#pragma unroll
    for (int i = 0; i < 8; i++) {
        float v = xs[i];
#pragma unroll
        for (int o = 16; o; o >>= 1) v += __shfl_xor_sync(0xffffffffu, v, o);
        if (lane == 0)
            g_xsumpart[blockIdx.y * 256 + bi0 + wid + 8 * i] = v;
    }
}

// ---------------- k_s3: fused split-K reduce + s (grid 256 = bi rows, 512 thr) -------
__global__ __launch_bounds__(512) void k_s3(const float* __restrict__ b3p)
{
    __shared__ float sPart[4][128];
    __shared__ float sT[128];
    __shared__ float sXs;
    __shared__ float smc[16][32];
    int bi = blockIdx.x, t = threadIdx.x;
    int b = bi >> 5, i = bi & 31;

    {
        int k = t & 127, p = t >> 7;
        float acc = 0.0f;
        const float* tp = g_Tpart + (size_t)(p * 8) * (NBI * H2D) + (size_t)bi * 128 + k;
#pragma unroll
        for (int sp = 0; sp < 8; sp++)
            acc += tp[(size_t)sp * (NBI * H2D)];
        sPart[p][k] = acc;
    }
    if (t < 32) {
        float v = g_xsumpart[t * 256 + bi];
#pragma unroll
        for (int off = 16; off; off >>= 1) v += __shfl_xor_sync(0xffffffffu, v, off);
        if (t == 0) sXs = v;
    }
    __syncthreads();
    if (t < 128)
        sT[t] = (sPart[0][t] + sPart[1][t]) + (sPart[2][t] + sPart[3][t]);
    __syncthreads();

    {
        int o = t & 31, kq = t >> 5;
        const float* wp = g_w3pt + (size_t)i * 4096 + (size_t)(kq * 8) * 32 + o;
        float acc = 0.0f;
#pragma unroll
        for (int j = 0; j < 8; j++)
            acc = fmaf(sT[kq * 8 + j], wp[j * 32], acc);
        smc[kq][o] = acc;
    }
    __syncthreads();
    if (t < 32) {
        float s = 0.0f;
#pragma unroll
        for (int kq = 0; kq < 16; kq++) s += smc[kq][t];
        int col = t * 32 + i;
        g_S[b * 1024 + col] = s + b3p[col] * sXs;
    }
}

// ---------------- k_u2: U[bo][k], c[bo] (grid 256 = (b,o), 128 thr; R12 proven) ------
__global__ __launch_bounds__(128) void k_u2(const float* __restrict__ w3q,
                                            const float* __restrict__ b3q)
{
    __shared__ float sW[128 * 33];
    __shared__ float sS[32];
    int bo = blockIdx.x, t = threadIdx.x;      // bo = b*32 + o
    int b = bo >> 5, o = bo & 31;
    for (int idx = t; idx < 4096; idx += 128) {
        int i = idx & 31, k = idx >> 5;
        sW[k * 33 + i] = w3q[k * 1024 + o * 32 + i];
    }
    if (t < 32) sS[t] = g_S[b * 1024 + o * 32 + t];
    __syncthreads();

    const float inv = 1.0f / (float)NX;
    {
        int k = t;
        float u = 0.0f;
#pragma unroll
        for (int ii = 0; ii < 32; ii++)
            u = fmaf(sS[ii], sW[k * 33 + ii], u);
        g_U[(size_t)bo * 128 + k] = u * inv;
    }
    if (t < 32) {
        float v = sS[t] * b3q[o * 32 + t];
#pragma unroll
        for (int off = 16; off; off >>= 1) v += __shfl_xor_sync(0xffffffffu, v, off);
        if (t == 0) g_c[bo] = v * inv;
    }
}

// ---------------- GEMM2 (mma.sync): out[bo][m] = psi[m,k] * U[bo,k] + c ----------------
__global__ __launch_bounds__(256, 2) void k_g2(float* __restrict__ out)
{
    extern __shared__ char dsm[];
    __shared__ float sc[64];
    uint32_t sb = smem_u32(dsm);
    int t = threadIdx.x, wid = t >> 5, lane = t & 31;
    int m0 = blockIdx.x * 128;
    int bo0 = blockIdx.y * 64;
    int m_w = (wid & 3) * 32;
    int j_w = (wid >> 2) * 32;
    int lrow = lane & 15, lcol = (lane >> 4) * 8;
    int grp = lane >> 2, tig = lane & 3;

    if (t < 64) sc[t] = g_c[bo0 + t];

    for (int idx = t; idx < 2048; idx += 256) {
        int row = idx >> 4, k8 = idx & 15;
        size_t ga = (size_t)(m0 + row) * H2D + k8 * 8;
        uint32_t off = (uint32_t)(row * ROWB + k8 * 16);
        *(uint4*)(dsm + G2_AHI + off) = *(const uint4*)(g_Apsi_hi + ga);
        *(uint4*)(dsm + G2_ALO + off) = *(const uint4*)(g_Apsi_lo + ga);
    }
    for (int idx = t; idx < 2048; idx += 256) {
        int row = idx >> 5, kq = idx & 31;
        float4 v = *(const float4*)(g_U + (size_t)(bo0 + row) * 128 + kq * 4);
        __nv_bfloat16 h0,h1,h2,h3,l0,l1,l2,l3;
        split1(v.x,h0,l0); split1(v.y,h1,l1); split1(v.z,h2,l2); split1(v.w,h3,l3);
        uint32_t off = (uint32_t)(row * ROWB + kq * 8);
        *(uint2*)(dsm + G2_BHI + off) = make_uint2(pack2(h0,h1), pack2(h2,h3));
        *(uint2*)(dsm + G2_BLO + off) = make_uint2(pack2(l0,l1), pack2(l2,l3));
    }
    __syncthreads();

    float C[2][4][4];
#pragma unroll
    for (int a = 0; a < 2; a++)
#pragma unroll
        for (int b = 0; b < 4; b++)
#pragma unroll
            for (int d = 0; d < 4; d++) C[a][b][d] = 0.0f;

#pragma unroll
    for (int ks = 0; ks < 8; ks++) {
        int c0 = ks * 16;
        uint32_t ah[8], al[8], bh[8], bl[8];
#pragma unroll
        for (int mi = 0; mi < 2; mi++) {
            uint32_t ro = (uint32_t)(((m_w + mi * 16 + lrow) * TSTR + c0 + lcol) * 2);
            ldm4(ah + mi * 4, sb + G2_AHI + ro);
            ldm4(al + mi * 4, sb + G2_ALO + ro);
        }
#pragma unroll
        for (int q = 0; q < 2; q++) {
            uint32_t ro = (uint32_t)(((j_w + q * 16 + lrow) * TSTR + c0 + lcol) * 2);
            ldm4(bh + q * 4, sb + G2_BHI + ro);
            ldm4(bl + q * 4, sb + G2_BLO + ro);
        }
#pragma unroll
        for (int mi = 0; mi < 2; mi++)
#pragma unroll
            for (int q = 0; q < 2; q++) {
                mma_bf16(C[mi][2*q],   ah + mi*4, bh[q*4+0], bh[q*4+2]);
                mma_bf16(C[mi][2*q],   ah + mi*4, bl[q*4+0], bl[q*4+2]);
                mma_bf16(C[mi][2*q],   al + mi*4, bh[q*4+0], bh[q*4+2]);
                mma_bf16(C[mi][2*q+1], ah + mi*4, bh[q*4+1], bh[q*4+3]);
                mma_bf16(C[mi][2*q+1], ah + mi*4, bl[q*4+1], bl[q*4+3]);
                mma_bf16(C[mi][2*q+1], al + mi*4, bh[q*4+1], bh[q*4+3]);
            }
    }
    __syncthreads();

    float* sO = (float*)dsm;
#pragma unroll
    for (int mi = 0; mi < 2; mi++)
#pragma unroll
        for (int jj = 0; jj < 4; jj++) {
            int j = j_w + jj * 8 + tig * 2;
            int i = m_w + mi * 16 + grp;
            sO[j * 132 + i]           = C[mi][jj][0];
            sO[(j + 1) * 132 + i]     = C[mi][jj][1];
            sO[j * 132 + i + 8]       = C[mi][jj][2];
            sO[(j + 1) * 132 + i + 8] = C[mi][jj][3];
        }
    __syncthreads();
    for (int idx = t; idx < 8192; idx += 256) {
        int i = idx & 127, j = idx >> 7;
        out[(size_t)(bo0 + j) * NX + m0 + i] = sO[j * 132 + i] + sc[j];
    }
}

// ---------------- launch ----------------
extern "C" void kernel_launch(void* const* d_in, const int* in_sizes, int n_in,
                              void* d_out, int out_size)
{
    const float* x      = (const float*)d_in[0];
    const float* phi_w1 = (const float*)d_in[1];
    const float* phi_b1 = (const float*)d_in[2];
    const float* phi_w2 = (const float*)d_in[3];
    const float* phi_b2 = (const float*)d_in[4];
    const float* phi_w3 = (const float*)d_in[5];
    const float* phi_b3 = (const float*)d_in[6];
    const float* psi_w1 = (const float*)d_in[7];
    const float* psi_b1 = (const float*)d_in[8];
    const float* psi_w2 = (const float*)d_in[9];
    const float* psi_b2 = (const float*)d_in[10];
    const float* psi_w3 = (const float*)d_in[11];
    const float* psi_b3 = (const float*)d_in[12];
    float* out = (float*)d_out;

    cudaFuncSetAttribute(k_mlp, cudaFuncAttributeMaxDynamicSharedMemorySize, MLP_SMEM);
    cudaFuncSetAttribute(k_g1,  cudaFuncAttributeMaxDynamicSharedMemorySize, G1_SMEM);
    cudaFuncSetAttribute(k_g2,  cudaFuncAttributeMaxDynamicSharedMemorySize, G2_SMEM);

    k_tr<<<H2D, 256>>>(phi_w3);
    k_mlp<<<dim3(NX / 128, 2), 256, MLP_SMEM>>>(phi_w1, phi_b1, phi_w2, phi_b2,
                                                psi_w1, psi_b1, psi_w2, psi_b2);
    k_g1<<<dim3(4, KSPLIT), 256, G1_SMEM>>>(x);
    k_s3<<<NBI, 512>>>(phi_b3);
    k_u2<<<NBO, 128>>>(psi_w3, psi_b3);
    k_g2<<<dim3(NX / 128, 4), 256, G2_SMEM>>>(out);
}

// round 17
// speedup vs baseline: 1.0669x; 1.0549x over previous
#include <cuda_runtime.h>
#include <cuda_bf16.h>
#include <cstdint>

#define NX    16384
#define CI    32
#define CO    32
#define H1D   64
#define H2D   128
#define NBI   256
#define NBO   256
#define KSPLIT 64

// ---------------- device scratch ----------------
__device__ __nv_bfloat16 g_Bphi_hi[H2D * NX];   // [k][n] phi hidden (relu'd), bf16 hi
__device__ __nv_bfloat16 g_Bphi_lo[H2D * NX];   // residual
__device__ __nv_bfloat16 g_Apsi_hi[NX * H2D];   // [m][k] psi hidden, bf16 hi
__device__ __nv_bfloat16 g_Apsi_lo[NX * H2D];
__device__ float g_Tpart[KSPLIT * NBI * H2D];   // [sp][bi][k]  8.4 MB
__device__ float g_xsumpart[KSPLIT * NBI];      // [sp][bi]
__device__ float g_w3pt[CI * H2D * CO];         // [i][k][o]  512 KB
__device__ float g_S[8 * CO * CI];              // [b][o*32+i]
__device__ float g_U[NBO * H2D];                // [b*32+o][k] (scaled 1/NX)
__device__ float g_c[NBO];                      // (scaled 1/NX)

// ---------------- helpers ----------------
__device__ __forceinline__ uint32_t smem_u32(const void* p) {
    uint32_t a;
    asm("{ .reg .u64 t; cvta.to.shared.u64 t, %1; cvt.u32.u64 %0, t; }" : "=r"(a) : "l"(p));
    return a;
}
__device__ __forceinline__ void ldm4(uint32_t* r, uint32_t addr) {
    asm volatile("ldmatrix.sync.aligned.m8n8.x4.shared.b16 {%0,%1,%2,%3}, [%4];"
                 : "=r"(r[0]), "=r"(r[1]), "=r"(r[2]), "=r"(r[3]) : "r"(addr));
}
__device__ __forceinline__ void mma_bf16(float* c, const uint32_t* a, uint32_t b0, uint32_t b1) {
    asm volatile("mma.sync.aligned.m16n8k16.row.col.f32.bf16.bf16.f32 "
                 "{%0,%1,%2,%3}, {%4,%5,%6,%7}, {%8,%9}, {%0,%1,%2,%3};"
                 : "+f"(c[0]), "+f"(c[1]), "+f"(c[2]), "+f"(c[3])
                 : "r"(a[0]), "r"(a[1]), "r"(a[2]), "r"(a[3]), "r"(b0), "r"(b1));
}
__device__ __forceinline__ uint32_t pack2(__nv_bfloat16 a, __nv_bfloat16 b) {
    return (uint32_t)__bfloat16_as_ushort(a) | ((uint32_t)__bfloat16_as_ushort(b) << 16);
}
__device__ __forceinline__ void split1(float v, __nv_bfloat16& h, __nv_bfloat16& l) {
    h = __float2bfloat16(v);
    l = __float2bfloat16(v - __bfloat162float(h));
}

// SMEM tile geometry for GEMM1/2 (bf16): row stride 136 elems (272 B)
#define TSTR 136
#define ROWB 272
// k_g1: A = x (64 rows), B = phi (128 rows)
#define G1_AHI 0
#define G1_ALO 17408
#define G1_BHI 34816
#define G1_BLO 69632
#define G1_SMEM 104448
// k_g2: A = psi (128 rows), B = U (64 rows)
#define G2_AHI 0
#define G2_ALO 34816
#define G2_BHI 69632
#define G2_BLO 87040
#define G2_SMEM 104448
// k_mlp: A = h1 (128 n x 64 j), B = w2T (128 k x 64 j), stride 72 elems (144 B)
#define MSTR 72
#define M_AHI 0
#define M_ALO 18432
#define M_BHI 36864
#define M_BLO 55296
#define MLP_SMEM 73728

// ---------------- K1: coordinate MLPs, layer2 on tensor pipe ----------------
__global__ __launch_bounds__(256) void k_mlp(
    const float* __restrict__ w1p, const float* __restrict__ b1p,
    const float* __restrict__ w2p, const float* __restrict__ b2p,
    const float* __restrict__ w1q, const float* __restrict__ b1q,
    const float* __restrict__ w2q, const float* __restrict__ b2q)
{
    extern __shared__ char dsm[];
    __shared__ float sW1[2 * H1D];
    __shared__ float sB1[H1D];
    __shared__ float sB2[H2D];
    uint32_t sb = smem_u32(dsm);

    const bool psi = (blockIdx.y != 0);
    const float* w1 = psi ? w1q : w1p;
    const float* b1 = psi ? b1q : b1p;
    const float* w2 = psi ? w2q : w2p;
    const float* b2 = psi ? b2q : b2p;

    int t = threadIdx.x, wid = t >> 5, lane = t & 31;
    int n0 = blockIdx.x * 128;

    if (t < 2 * H1D) sW1[t] = w1[t];
    if (t < H1D)     sB1[t] = b1[t];
    if (t < H2D)     sB2[t] = b2[t];

    for (int idx = t; idx < H1D * H2D; idx += 256) {
        int k = idx & 127, j = idx >> 7;
        float v = w2[j * 128 + k];
        __nv_bfloat16 h, l; split1(v, h, l);
        uint32_t off = (uint32_t)((k * MSTR + j) * 2);
        *(__nv_bfloat16*)(dsm + M_BHI + off) = h;
        *(__nv_bfloat16*)(dsm + M_BLO + off) = l;
    }
    __syncthreads();

    {
        int nl = t >> 1;
        int n = n0 + nl;
        int j0 = (t & 1) * 32;
        const float inv = 1.0f / 127.0f;
        float gx = (float)(n >> 7) * inv;
        float gy = (float)(n & 127) * inv;
#pragma unroll
        for (int jj = 0; jj < 32; jj += 2) {
            int j = j0 + jj;
            float v0 = fmaxf(fmaf(gx, sW1[j],     fmaf(gy, sW1[H1D + j],     sB1[j])),     0.0f);
            float v1 = fmaxf(fmaf(gx, sW1[j + 1], fmaf(gy, sW1[H1D + j + 1], sB1[j + 1])), 0.0f);
            __nv_bfloat16 h0, l0, h1v, l1; split1(v0, h0, l0); split1(v1, h1v, l1);
            uint32_t off = (uint32_t)((nl * MSTR + j) * 2);
            *(uint32_t*)(dsm + M_AHI + off) = pack2(h0, h1v);
            *(uint32_t*)(dsm + M_ALO + off) = pack2(l0, l1);
        }
    }
    __syncthreads();

    int m_w = (wid & 3) * 32;
    int j_w = (wid >> 2) * 64;
    int lrow = lane & 15, lcol = (lane >> 4) * 8;
    int grp = lane >> 2, tig = lane & 3;

    float C[2][8][4];
#pragma unroll
    for (int a = 0; a < 2; a++)
#pragma unroll
        for (int b = 0; b < 8; b++)
#pragma unroll
            for (int d = 0; d < 4; d++) C[a][b][d] = 0.0f;

#pragma unroll
    for (int ks = 0; ks < 4; ks++) {
        int c0 = ks * 16;
        uint32_t ah[8], al[8], bh[16], bl[16];
#pragma unroll
        for (int mi = 0; mi < 2; mi++) {
            uint32_t ro = (uint32_t)(((m_w + mi * 16 + lrow) * MSTR + c0 + lcol) * 2);
            ldm4(ah + mi * 4, sb + M_AHI + ro);
            ldm4(al + mi * 4, sb + M_ALO + ro);
        }
#pragma unroll
        for (int q = 0; q < 4; q++) {
            uint32_t ro = (uint32_t)(((j_w + q * 16 + lrow) * MSTR + c0 + lcol) * 2);
            ldm4(bh + q * 4, sb + M_BHI + ro);
            ldm4(bl + q * 4, sb + M_BLO + ro);
        }
#pragma unroll
        for (int mi = 0; mi < 2; mi++)
#pragma unroll
            for (int q = 0; q < 4; q++) {
                mma_bf16(C[mi][2*q],   ah + mi*4, bh[q*4+0], bh[q*4+2]);
                mma_bf16(C[mi][2*q],   ah + mi*4, bl[q*4+0], bl[q*4+2]);
                mma_bf16(C[mi][2*q],   al + mi*4, bh[q*4+0], bh[q*4+2]);
                mma_bf16(C[mi][2*q+1], ah + mi*4, bh[q*4+1], bh[q*4+3]);
                mma_bf16(C[mi][2*q+1], ah + mi*4, bl[q*4+1], bl[q*4+3]);
                mma_bf16(C[mi][2*q+1], al + mi*4, bh[q*4+1], bh[q*4+3]);
            }
    }
    __syncthreads();

    float* sO = (float*)dsm;
#pragma unroll
    for (int mi = 0; mi < 2; mi++)
#pragma unroll
        for (int jj = 0; jj < 8; jj++) {
            int j = j_w + jj * 8 + tig * 2;
            int i = m_w + mi * 16 + grp;
            sO[i * 133 + j]           = C[mi][jj][0];
            sO[i * 133 + j + 1]       = C[mi][jj][1];
            sO[(i + 8) * 133 + j]     = C[mi][jj][2];
            sO[(i + 8) * 133 + j + 1] = C[mi][jj][3];
        }
    __syncthreads();

    if (!psi) {
        for (int idx = t; idx < 16384; idx += 256) {
            int k = idx >> 7, r = idx & 127;
            float v = fmaxf(sO[r * 133 + k] + sB2[k], 0.0f);
            __nv_bfloat16 h, l; split1(v, h, l);
            size_t a = (size_t)k * NX + n0 + r;
            g_Bphi_hi[a] = h;
            g_Bphi_lo[a] = l;
        }
    } else {
        for (int idx = t; idx < 16384; idx += 256) {
            int row = idx >> 7, k = idx & 127;
            float v = fmaxf(sO[row * 133 + k] + sB2[k], 0.0f);
            __nv_bfloat16 h, l; split1(v, h, l);
            size_t a = (size_t)(n0 + row) * H2D + k;
            g_Apsi_hi[a] = h;
            g_Apsi_lo[a] = l;
        }
    }
}

// ---------------- k_tr: w3p[k][o*32+i] -> w3pt[i][k][o] (both sides coalesced) ------
__global__ __launch_bounds__(256) void k_tr(const float* __restrict__ w3p)
{
    __shared__ float sm[32 * 33];          // [o][i] pad 33
    int k = blockIdx.x, t = threadIdx.x;
    for (int it = 0; it < 4; it++) {
        int col = it * 256 + t;            // coalesced read
        sm[(col >> 5) * 33 + (col & 31)] = w3p[k * 1024 + col];
    }
    __syncthreads();
    for (int it = 0; it < 4; it++) {
        int idx = it * 256 + t;
        int i = idx >> 5, o = idx & 31;    // consecutive t -> consecutive o: coalesced write
        g_w3pt[i * 4096 + k * 32 + o] = sm[o * 33 + i];
    }
}

// ---------------- GEMM1 (mma.sync) + fused xsum partials -----------------------------
// grid (4 bi-tiles of 64, 64 splits) = 256 CTAs. Per CTA: 64 bi x 128 k, 256 n (2 chunks).
__global__ __launch_bounds__(256, 2) void k_g1(const float* __restrict__ x)
{
    extern __shared__ char dsm[];
    uint32_t sb = smem_u32(dsm);
    int t = threadIdx.x, wid = t >> 5, lane = t & 31;
    int bi0 = blockIdx.x * 64;
    int n0 = blockIdx.y * 256;
    int m_w = (wid & 1) * 32;
    int j_w = (wid >> 1) * 32;
    int lrow = lane & 15, lcol = (lane >> 4) * 8;
    int grp = lane >> 2, tig = lane & 3;

    float C[2][4][4];
#pragma unroll
    for (int a = 0; a < 2; a++)
#pragma unroll
        for (int b = 0; b < 4; b++)
#pragma unroll
            for (int d = 0; d < 4; d++) C[a][b][d] = 0.0f;

    float xs[8];
#pragma unroll
    for (int i = 0; i < 8; i++) xs[i] = 0.0f;

    for (int ch = 0; ch < 2; ch++) {
        int nb = n0 + ch * 128;
#pragma unroll
        for (int it = 0; it < 8; it++) {
            int idx = t + it * 256;
            int row = idx >> 5, nq = idx & 31;
            float4 v = *(const float4*)(x + (size_t)(bi0 + row) * NX + nb + nq * 4);
            xs[it] += (v.x + v.y) + (v.z + v.w);
            __nv_bfloat16 h0,h1,h2,h3,l0,l1,l2,l3;
            split1(v.x,h0,l0); split1(v.y,h1,l1); split1(v.z,h2,l2); split1(v.w,h3,l3);
            uint32_t off = (uint32_t)(row * ROWB + nq * 8);
            *(uint2*)(dsm + G1_AHI + off) = make_uint2(pack2(h0,h1), pack2(h2,h3));
            *(uint2*)(dsm + G1_ALO + off) = make_uint2(pack2(l0,l1), pack2(l2,l3));
        }
        for (int idx = t; idx < 2048; idx += 256) {
            int row = idx >> 4, n8 = idx & 15;
            size_t ga = (size_t)row * NX + nb + n8 * 8;
            uint32_t off = (uint32_t)(row * ROWB + n8 * 16);
            *(uint4*)(dsm + G1_BHI + off) = *(const uint4*)(g_Bphi_hi + ga);
            *(uint4*)(dsm + G1_BLO + off) = *(const uint4*)(g_Bphi_lo + ga);
        }
        __syncthreads();

#pragma unroll
        for (int ks = 0; ks < 8; ks++) {
            int c0 = ks * 16;
            uint32_t ah[8], al[8], bh[8], bl[8];
#pragma unroll
            for (int mi = 0; mi < 2; mi++) {
                uint32_t ro = (uint32_t)(((m_w + mi * 16 + lrow) * TSTR + c0 + lcol) * 2);
                ldm4(ah + mi * 4, sb + G1_AHI + ro);
                ldm4(al + mi * 4, sb + G1_ALO + ro);
            }
#pragma unroll
            for (int q = 0; q < 2; q++) {
                uint32_t ro = (uint32_t)(((j_w + q * 16 + lrow) * TSTR + c0 + lcol) * 2);
                ldm4(bh + q * 4, sb + G1_BHI + ro);
                ldm4(bl + q * 4, sb + G1_BLO + ro);
            }
#pragma unroll
            for (int mi = 0; mi < 2; mi++)
#pragma unroll
                for (int q = 0; q < 2; q++) {
                    mma_bf16(C[mi][2*q],   ah + mi*4, bh[q*4+0], bh[q*4+2]);
                    mma_bf16(C[mi][2*q],   ah + mi*4, bl[q*4+0], bl[q*4+2]);
                    mma_bf16(C[mi][2*q],   al + mi*4, bh[q*4+0], bh[q*4+2]);
                    mma_bf16(C[mi][2*q+1], ah + mi*4, bh[q*4+1], bh[q*4+3]);
                    mma_bf16(C[mi][2*q+1], ah + mi*4, bl[q*4+1], bl[q*4+3]);
                    mma_bf16(C[mi][2*q+1], al + mi*4, bh[q*4+1], bh[q*4+3]);
                }
        }
        __syncthreads();
    }

#pragma unroll
    for (int mi = 0; mi < 2; mi++)
#pragma unroll
        for (int jj = 0; jj < 4; jj++) {
            int j = j_w + jj * 8 + tig * 2;
            int bi_l = m_w + mi * 16 + grp;
            size_t a0 = ((size_t)blockIdx.y * 256 + bi0 + bi_l) * 128 + j;
            *(float2*)(g_Tpart + a0)          = make_float2(C[mi][jj][0], C[mi][jj][1]);
            *(float2*)(g_Tpart + a0 + 8*128)  = make_float2(C[mi][jj][2], C[mi][jj][3]);
        }

#pragma unroll
    for (int i = 0; i < 8; i++) {
        float v = xs[i];
#pragma unroll
        for (int o = 16; o; o >>= 1) v += __shfl_xor_sync(0xffffffffu, v, o);
        if (lane == 0)
            g_xsumpart[blockIdx.y * 256 + bi0 + wid + 8 * i] = v;
    }
}

// ---------------- k_s3: fused split-K reduce + s (grid 256 = bi rows, 512 thr) -------
__global__ __launch_bounds__(512) void k_s3(const float* __restrict__ b3p)
{
    __shared__ float sPart[4][128];
    __shared__ float sT[128];
    __shared__ float sXs;
    __shared__ float smc[16][32];
    int bi = blockIdx.x, t = threadIdx.x;
    int b = bi >> 5, i = bi & 31;

    {
        int k = t & 127, p = t >> 7;
        float acc = 0.0f;
        const float* tp = g_Tpart + (size_t)(p * 16) * (NBI * H2D) + (size_t)bi * 128 + k;
#pragma unroll
        for (int sp = 0; sp < 16; sp++)
            acc += tp[(size_t)sp * (NBI * H2D)];
        sPart[p][k] = acc;
    }
    if (t < 32) {
        float v = g_xsumpart[t * 256 + bi] + g_xsumpart[(t + 32) * 256 + bi];
#pragma unroll
        for (int off = 16; off; off >>= 1) v += __shfl_xor_sync(0xffffffffu, v, off);
        if (t == 0) sXs = v;
    }
    __syncthreads();
    if (t < 128)
        sT[t] = (sPart[0][t] + sPart[1][t]) + (sPart[2][t] + sPart[3][t]);
    __syncthreads();

    {
        int o = t & 31, kq = t >> 5;
        const float* wp = g_w3pt + (size_t)i * 4096 + (size_t)(kq * 8) * 32 + o;
        float acc = 0.0f;
#pragma unroll
        for (int j = 0; j < 8; j++)
            acc = fmaf(sT[kq * 8 + j], wp[j * 32], acc);
        smc[kq][o] = acc;
    }
    __syncthreads();
    if (t < 32) {
        float s = 0.0f;
#pragma unroll
        for (int kq = 0; kq < 16; kq++) s += smc[kq][t];
        int col = t * 32 + i;
        g_S[b * 1024 + col] = s + b3p[col] * sXs;
    }
}

// ---------------- k_u2: U[bo][k], c[bo] (grid 256 = (b,o), 128 thr; proven) ----------
__global__ __launch_bounds__(128) void k_u2(const float* __restrict__ w3q,
                                            const float* __restrict__ b3q)
{
    __shared__ float sW[128 * 33];
    __shared__ float sS[32];
    int bo = blockIdx.x, t = threadIdx.x;      // bo = b*32 + o
    int b = bo >> 5, o = bo & 31;
    for (int idx = t; idx < 4096; idx += 128) {
        int i = idx & 31, k = idx >> 5;
        sW[k * 33 + i] = w3q[k * 1024 + o * 32 + i];
    }
    if (t < 32) sS[t] = g_S[b * 1024 + o * 32 + t];
    __syncthreads();

    const float inv = 1.0f / (float)NX;
    {
        int k = t;
        float u = 0.0f;
#pragma unroll
        for (int ii = 0; ii < 32; ii++)
            u = fmaf(sS[ii], sW[k * 33 + ii], u);
        g_U[(size_t)bo * 128 + k] = u * inv;
    }
    if (t < 32) {
        float v = sS[t] * b3q[o * 32 + t];
#pragma unroll
        for (int off = 16; off; off >>= 1) v += __shfl_xor_sync(0xffffffffu, v, off);
        if (t == 0) g_c[bo] = v * inv;
    }
}

// ---------------- GEMM2 (mma.sync): out[bo][m] = psi[m,k] * U[bo,k] + c ----------------
__global__ __launch_bounds__(256, 2) void k_g2(float* __restrict__ out)
{
    extern __shared__ char dsm[];
    __shared__ float sc[64];
    uint32_t sb = smem_u32(dsm);
    int t = threadIdx.x, wid = t >> 5, lane = t & 31;
    int m0 = blockIdx.x * 128;
    int bo0 = blockIdx.y * 64;
    int m_w = (wid & 3) * 32;
    int j_w = (wid >> 2) * 32;
    int lrow = lane & 15, lcol = (lane >> 4) * 8;
    int grp = lane >> 2, tig = lane & 3;

    if (t < 64) sc[t] = g_c[bo0 + t];

    for (int idx = t; idx < 2048; idx += 256) {
        int row = idx >> 4, k8 = idx & 15;
        size_t ga = (size_t)(m0 + row) * H2D + k8 * 8;
        uint32_t off = (uint32_t)(row * ROWB + k8 * 16);
        *(uint4*)(dsm + G2_AHI + off) = *(const uint4*)(g_Apsi_hi + ga);
        *(uint4*)(dsm + G2_ALO + off) = *(const uint4*)(g_Apsi_lo + ga);
    }
    for (int idx = t; idx < 2048; idx += 256) {
        int row = idx >> 5, kq = idx & 31;
        float4 v = *(const float4*)(g_U + (size_t)(bo0 + row) * 128 + kq * 4);
        __nv_bfloat16 h0,h1,h2,h3,l0,l1,l2,l3;
        split1(v.x,h0,l0); split1(v.y,h1,l1); split1(v.z,h2,l2); split1(v.w,h3,l3);
        uint32_t off = (uint32_t)(row * ROWB + kq * 8);
        *(uint2*)(dsm + G2_BHI + off) = make_uint2(pack2(h0,h1), pack2(h2,h3));
        *(uint2*)(dsm + G2_BLO + off) = make_uint2(pack2(l0,l1), pack2(l2,l3));
    }
    __syncthreads();

    float C[2][4][4];
#pragma unroll
    for (int a = 0; a < 2; a++)
#pragma unroll
        for (int b = 0; b < 4; b++)
#pragma unroll
            for (int d = 0; d < 4; d++) C[a][b][d] = 0.0f;

#pragma unroll
    for (int ks = 0; ks < 8; ks++) {
        int c0 = ks * 16;
        uint32_t ah[8], al[8], bh[8], bl[8];
#pragma unroll
        for (int mi = 0; mi < 2; mi++) {
            uint32_t ro = (uint32_t)(((m_w + mi * 16 + lrow) * TSTR + c0 + lcol) * 2);
            ldm4(ah + mi * 4, sb + G2_AHI + ro);
            ldm4(al + mi * 4, sb + G2_ALO + ro);
        }
#pragma unroll
        for (int q = 0; q < 2; q++) {
            uint32_t ro = (uint32_t)(((j_w + q * 16 + lrow) * TSTR + c0 + lcol) * 2);
            ldm4(bh + q * 4, sb + G2_BHI + ro);
            ldm4(bl + q * 4, sb + G2_BLO + ro);
        }
#pragma unroll
        for (int mi = 0; mi < 2; mi++)
#pragma unroll
            for (int q = 0; q < 2; q++) {
                mma_bf16(C[mi][2*q],   ah + mi*4, bh[q*4+0], bh[q*4+2]);
                mma_bf16(C[mi][2*q],   ah + mi*4, bl[q*4+0], bl[q*4+2]);
                mma_bf16(C[mi][2*q],   al + mi*4, bh[q*4+0], bh[q*4+2]);
                mma_bf16(C[mi][2*q+1], ah + mi*4, bh[q*4+1], bh[q*4+3]);
                mma_bf16(C[mi][2*q+1], ah + mi*4, bl[q*4+1], bl[q*4+3]);
                mma_bf16(C[mi][2*q+1], al + mi*4, bh[q*4+1], bh[q*4+3]);
            }
    }
    __syncthreads();

    float* sO = (float*)dsm;
#pragma unroll
    for (int mi = 0; mi < 2; mi++)
#pragma unroll
        for (int jj = 0; jj < 4; jj++) {
            int j = j_w + jj * 8 + tig * 2;
            int i = m_w + mi * 16 + grp;
            sO[j * 132 + i]           = C[mi][jj][0];
            sO[(j + 1) * 132 + i]     = C[mi][jj][1];
            sO[j * 132 + i + 8]       = C[mi][jj][2];
            sO[(j + 1) * 132 + i + 8] = C[mi][jj][3];
        }
    __syncthreads();
    for (int idx = t; idx < 8192; idx += 256) {
        int i = idx & 127, j = idx >> 7;
        out[(size_t)(bo0 + j) * NX + m0 + i] = sO[j * 132 + i] + sc[j];
    }
}

// ---------------- launch ----------------
extern "C" void kernel_launch(void* const* d_in, const int* in_sizes, int n_in,
                              void* d_out, int out_size)
{
    const float* x      = (const float*)d_in[0];
    const float* phi_w1 = (const float*)d_in[1];
    const float* phi_b1 = (const float*)d_in[2];
    const float* phi_w2 = (const float*)d_in[3];
    const float* phi_b2 = (const float*)d_in[4];
    const float* phi_w3 = (const float*)d_in[5];
    const float* phi_b3 = (const float*)d_in[6];
    const float* psi_w1 = (const float*)d_in[7];
    const float* psi_b1 = (const float*)d_in[8];
    const float* psi_w2 = (const float*)d_in[9];
    const float* psi_b2 = (const float*)d_in[10];
    const float* psi_w3 = (const float*)d_in[11];
    const float* psi_b3 = (const float*)d_in[12];
    float* out = (float*)d_out;

    cudaFuncSetAttribute(k_mlp, cudaFuncAttributeMaxDynamicSharedMemorySize, MLP_SMEM);
    cudaFuncSetAttribute(k_g1,  cudaFuncAttributeMaxDynamicSharedMemorySize, G1_SMEM);
    cudaFuncSetAttribute(k_g2,  cudaFuncAttributeMaxDynamicSharedMemorySize, G2_SMEM);

    k_tr<<<H2D, 256>>>(phi_w3);
    k_mlp<<<dim3(NX / 128, 2), 256, MLP_SMEM>>>(phi_w1, phi_b1, phi_w2, phi_b2,
                                                psi_w1, psi_b1, psi_w2, psi_b2);
    k_g1<<<dim3(4, KSPLIT), 256, G1_SMEM>>>(x);
    k_s3<<<NBI, 512>>>(phi_b3);
    k_u2<<<NBO, 128>>>(psi_w3, psi_b3);
    k_g2<<<dim3(NX / 128, 4), 256, G2_SMEM>>>(out);
}